// round 10
// baseline (speedup 1.0000x reference)
#include <cuda_runtime.h>
#include <cuda_bf16.h>
#include <math.h>
#include <stdint.h>

// ---------------------------------------------------------------------------
// FullyConnectedTP: e3nn fully connected tensor product
//  IN  = 64x0e + 32x1o + 16x2e (240)  SH = 1x0e+1x1o+1x2e (9)  OUT = 240
//  per-edge weights 13824 fp32, N_EDGES = 16384
//
// R6 design: persistent-ish blocks (grid 1024, 16 edges each), weights
// streamed into double-buffered SMEM with cp.async.bulk + mbarrier so DRAM
// traffic is continuous (breaks the phase-locked load/compute alternation
// that capped DRAM at 59.7% in R2/R3/R5).
// ---------------------------------------------------------------------------

#define NPATH 11

__constant__ int C_L1[NPATH]    = {0,0,0,1,1,1,1,2,2,2,2};
__constant__ int C_L2[NPATH]    = {0,1,2,0,1,1,2,0,1,2,2};
__constant__ int C_L3[NPATH]    = {0,1,2,1,0,2,1,2,1,0,2};
__constant__ int C_COFF[NPATH]  = {0,1,10,35,44,53,98,143,168,213,238};
__constant__ int C_CSZ[NPATH]   = {1,9,25,9,9,45,45,25,45,25,125};
__constant__ int C_DOFF[NPATH]  = {0,1,4,9,18,21,36,45,70,85,90};
__constant__ int C_TOFF[NPATH]  = {0,64,256,576,672,704,864,960,1040,1088,1104};
__constant__ int C_INOFF[NPATH] = {0,0,0,64,64,64,64,160,160,160,160};
__constant__ int C_SHOFF[NPATH] = {0,1,4,0,1,1,4,0,1,4,4};

__device__ float    g_w3j[363];
__device__ unsigned g_desc2[115];
__device__ unsigned g_desc3[1184];

// ---------------------------------------------------------------------------
// Setup kernel (FP32): wigner 3j + descriptor tables (same math as reference)
// ---------------------------------------------------------------------------

__device__ __forceinline__ float d_fact(int n) {
    const float F[9] = {1.f, 1.f, 2.f, 6.f, 24.f, 120.f, 720.f, 5040.f, 40320.f};
    return F[n];
}

__device__ float su2_cg_coeff(int j1, int m1, int j2, int m2, int j3, int m3) {
    if (m3 != m1 + m2) return 0.0f;
    int vmin = -j1 + j2 + m3;
    if (-j1 + m1 > vmin) vmin = -j1 + m1;
    if (0 > vmin) vmin = 0;
    int vmax = j2 + j3 + m1;
    if (j3 - j1 + j2 < vmax) vmax = j3 - j1 + j2;
    if (j3 + m3 < vmax) vmax = j3 + m3;
    float C = sqrtf((float)(2 * j3 + 1)
                    * d_fact(j3 + j1 - j2) * d_fact(j3 - j1 + j2) * d_fact(j1 + j2 - j3)
                    * d_fact(j3 + m3) * d_fact(j3 - m3)
                    / (d_fact(j1 + j2 + j3 + 1) * d_fact(j1 - m1) * d_fact(j1 + m1)
                       * d_fact(j2 - m2) * d_fact(j2 + m2)));
    float S = 0.0f;
    for (int v = vmin; v <= vmax; ++v) {
        float sgn = ((v + j2 + m2) & 1) ? -1.0f : 1.0f;
        S += sgn * d_fact(j2 + j3 + m1 - v) * d_fact(j1 - m1 + v)
             / (d_fact(v) * d_fact(j3 - j1 + j2 - v) * d_fact(j3 + m3 - v)
                * d_fact(v + j1 - j2 - m3));
    }
    return C * S;
}

__device__ void q_entry(int l, int r, int c, float& qre, float& qim) {
    const float s = 0.70710678118654752440f;
    float re = 0.0f, im = 0.0f;
    int m = r - l;
    if (m < 0) {
        if (c == l - m)      re = s;
        else if (c == l + m) im = -s;
    } else if (m == 0) {
        if (c == l) re = 1.0f;
    } else {
        float sg = (m & 1) ? -1.0f : 1.0f;
        if (c == l + m)      re = sg * s;
        else if (c == l - m) im = sg * s;
    }
    float ore, oim;
    switch (l & 3) {
        case 0: ore =  re; oim =  im; break;
        case 1: ore =  im; oim = -re; break;
        case 2: ore = -re; oim = -im; break;
        default: ore = -im; oim =  re; break;
    }
    qre = ore; qim = oim;
}

__global__ void w3j_setup_kernel() {
    __shared__ float sC[363];
    __shared__ float sInv[NPATH];
    int e = threadIdx.x;

    if (e < 363) {
        int p = 0;
        while (p < NPATH - 1 && e >= C_COFF[p + 1]) ++p;
        int local = e - C_COFF[p];
        int l1 = C_L1[p], l2 = C_L2[p], l3 = C_L3[p];
        int d2 = 2 * l2 + 1, d3 = 2 * l3 + 1;
        int a = local / (d2 * d3);
        int rem = local - a * (d2 * d3);
        int b = rem / d3;
        int c = rem - b * d3;
        float acc = 0.0f;
        for (int i = 0; i <= 2 * l1; ++i) {
            for (int k = 0; k <= 2 * l2; ++k) {
                int m1 = i - l1, m2 = k - l2, m3 = m1 + m2;
                if (m3 < -l3 || m3 > l3) continue;
                int n = l3 + m3;
                float cg = su2_cg_coeff(l1, m1, l2, m2, l3, m3);
                if (cg == 0.0f) continue;
                float q1r, q1i, q2r, q2i, q3r, q3i;
                q_entry(l1, i, a, q1r, q1i);
                q_entry(l2, k, b, q2r, q2i);
                q_entry(l3, c, n, q3r, q3i);
                q3i = -q3i;
                float tr = q1r * q2r - q1i * q2i;
                float ti = q1r * q2i + q1i * q2r;
                float ur = tr * q3r - ti * q3i;
                acc += ur * cg;
            }
        }
        sC[e] = acc;
    }
    __syncthreads();
    if (e < NPATH) {
        float ss = 0.f;
        int base = C_COFF[e], sz = C_CSZ[e];
        for (int q = 0; q < sz; ++q) ss += sC[base + q] * sC[base + q];
        sInv[e] = rsqrtf(ss);
    }
    __syncthreads();
    if (e < 363) {
        int p = 0;
        while (p < NPATH - 1 && e >= C_COFF[p + 1]) ++p;
        g_w3j[e] = sC[e] * sInv[p];
    }

    if (e < 115) {
        int p = 0;
        while (p < NPATH - 1 && e >= C_DOFF[p + 1]) ++p;
        int local = e - C_DOFF[p];
        int d2 = 2 * C_L2[p] + 1, d3 = 2 * C_L3[p] + 1;
        int i = local / d3;
        int k = local - i * d3;
        unsigned base = C_COFF[p] + (i * d2) * d3 + k;
        g_desc2[e] = base | ((unsigned)d3 << 10) | ((unsigned)d2 << 13)
                   | ((unsigned)C_SHOFF[p] << 16);
    }
    for (int e3 = e; e3 < 1184; e3 += blockDim.x) {
        int p = 0;
        while (p < NPATH - 1 && e3 >= C_TOFF[p + 1]) ++p;
        int local = e3 - C_TOFF[p];
        int d1 = 2 * C_L1[p] + 1, d3 = 2 * C_L3[p] + 1;
        int u = local / d3;
        int k = local - u * d3;
        unsigned su = C_INOFF[p] + u * d1;
        unsigned dk = C_DOFF[p] + k;
        g_desc3[e3] = su | (dk << 8) | ((unsigned)d3 << 15) | ((unsigned)d1 << 18);
    }
}

// ---------------------------------------------------------------------------
// Main kernel
// ---------------------------------------------------------------------------

#define PW0 0.09449111825230679f
#define PW1 0.14433756729740643f
#define PW2 0.19764235376052372f

#define WBYTES 55296u   /* 13824 floats */

// shared memory layout (bytes)
#define SM_BUF0   0
#define SM_BUF1   55296
#define SM_U      110592
#define SM_V      (SM_U + 960)        /* 111552 */
#define SM_D      (SM_V + 48)         /* 111600 */
#define SM_TMP    (SM_D + 464)        /* 112064 */
#define SM_W3J    (SM_TMP + 4736)     /* 116800 */
#define SM_DESC2  (SM_W3J + 1456)     /* 118256 */
#define SM_DESC3  (SM_DESC2 + 464)    /* 118720 */
#define SM_RED    (SM_DESC3 + 4736)   /* 123456 */
#define SM_MBAR   (SM_RED + 36864)    /* 160320 */
#define SM_TOTAL  (SM_MBAR + 16)      /* 160336 */

__device__ __forceinline__ uint32_t smem_u32(const void* p) {
    uint32_t a;
    asm("{ .reg .u64 t; cvta.to.shared.u64 t, %1; cvt.u32.u64 %0, t; }" : "=r"(a) : "l"(p));
    return a;
}

__device__ __forceinline__ void mbar_init(uint32_t mbar, uint32_t count) {
    asm volatile("mbarrier.init.shared.b64 [%0], %1;" :: "r"(mbar), "r"(count) : "memory");
}

__device__ __forceinline__ void tma_issue(uint32_t dst, const float* src, uint32_t mbar) {
    asm volatile("mbarrier.arrive.expect_tx.shared.b64 _, [%0], %1;"
                 :: "r"(mbar), "r"(WBYTES) : "memory");
    asm volatile("cp.async.bulk.shared::cluster.global.mbarrier::complete_tx::bytes "
                 "[%0], [%1], %2, [%3];"
                 :: "r"(dst), "l"(src), "r"(WBYTES), "r"(mbar) : "memory");
}

__device__ __forceinline__ void mbar_wait(uint32_t mbar, uint32_t parity) {
    uint32_t done;
    asm volatile("{\n .reg .pred p;\n"
                 " mbarrier.try_wait.parity.acquire.cta.shared::cta.b64 p, [%1], %2;\n"
                 " selp.b32 %0, 1, 0, p;\n}"
                 : "=r"(done) : "r"(mbar), "r"(parity) : "memory");
    while (!done) {
        asm volatile("{\n .reg .pred p;\n"
                     " mbarrier.try_wait.parity.acquire.cta.shared::cta.b64 p, [%1], %2, 0x989680;\n"
                     " selp.b32 %0, 1, 0, p;\n}"
                     : "=r"(done) : "r"(mbar), "r"(parity) : "memory");
    }
}

__global__ __launch_bounds__(256, 1) void tp_main_kernel(
    const float* __restrict__ U, const float* __restrict__ V,
    const float* __restrict__ W, float* __restrict__ O, int n_edges)
{
    extern __shared__ char smem[];
    float*    s_u     = (float*)(smem + SM_U);
    float*    s_v     = (float*)(smem + SM_V);
    float*    s_D     = (float*)(smem + SM_D);
    float*    s_tmp   = (float*)(smem + SM_TMP);
    float*    s_w3j   = (float*)(smem + SM_W3J);
    unsigned* s_desc2 = (unsigned*)(smem + SM_DESC2);
    unsigned* s_desc3 = (unsigned*)(smem + SM_DESC3);
    float*    s_red   = (float*)(smem + SM_RED);

    const int t   = threadIdx.x;
    const int bid = blockIdx.x;
    const int stride = gridDim.x;

    const uint32_t sbase = smem_u32(smem);
    const uint32_t mbar0 = sbase + SM_MBAR;
    const uint32_t mbar1 = sbase + SM_MBAR + 8;

    // one-time per-block: init mbarriers, copy constant tables to shared
    if (t == 0) { mbar_init(mbar0, 1); mbar_init(mbar1, 1); }
    for (int e = t; e < 363;  e += 256) s_w3j[e]   = g_w3j[e];
    for (int e = t; e < 115;  e += 256) s_desc2[e] = g_desc2[e];
    for (int e = t; e < 1184; e += 256) s_desc3[e] = g_desc3[e];
    __syncthreads();

    // prologue: kick off first two weight streams
    if (t == 0) {
        if (bid < n_edges)
            tma_issue(sbase + SM_BUF0, W + (size_t)bid * 13824, mbar0);
        if (bid + stride < n_edges)
            tma_issue(sbase + SM_BUF1, W + (size_t)(bid + stride) * 13824, mbar1);
    }

    // prefetch u/v for first edge into registers
    float u_reg = 0.f, v_reg = 0.f;
    if (bid < n_edges) {
        if (t < 240) u_reg = U[(size_t)bid * 240 + t];
        if (t >= 240 && t < 249) v_reg = V[(size_t)bid * 9 + (t - 240)];
    }

    // per-thread phase-4 constants
    const int cA = t & 15, rA = t >> 4;
    const int cB = t & 7,  rB = t >> 3;
    const int cC = t & 3,  rC = t >> 2;
    int wbaseC, tbaseC, uC;
    if (rC < 32)      { uC = rC;      wbaseC = 2560; tbaseC = 704;  }
    else if (rC < 48) { uC = rC - 32; wbaseC = 2944; tbaseC = 960;  }
    else              { uC = rC - 48; wbaseC = 3392; tbaseC = 1104; }

    int i = 0;
    for (int z = bid; z < n_edges; z += stride, ++i) {
        // stage u/v (prefetched last iteration)
        if (t < 240) s_u[t] = u_reg;
        if (t >= 240 && t < 249) s_v[t - 240] = v_reg;
        __syncthreads();

        // prefetch next edge's u/v
        int zn = z + stride;
        if (zn < n_edges) {
            if (t < 240) u_reg = U[(size_t)zn * 240 + t];
            if (t >= 240 && t < 249) v_reg = V[(size_t)zn * 9 + (t - 240)];
        }

        // phase 2: D
        if (t < 115) {
            unsigned d = s_desc2[t];
            int base = d & 1023;
            int d3   = (d >> 10) & 7;
            int d2   = (d >> 13) & 7;
            int sh   = (d >> 16) & 15;
            float acc = 0.f;
            for (int j = 0; j < d2; ++j)
                acc += s_w3j[base + j * d3] * s_v[sh + j];
            s_D[t] = acc;
        }
        __syncthreads();

        // phase 3: tmp
        #pragma unroll
        for (int jj = 0; jj < 5; ++jj) {
            int e = t + 256 * jj;
            if (e < 1184) {
                unsigned d = s_desc3[e];
                int su = d & 255;
                int dk = (d >> 8) & 127;
                int d3 = (d >> 15) & 7;
                int d1 = (d >> 18) & 7;
                float acc = 0.f;
                for (int ii = 0; ii < d1; ++ii)
                    acc += s_u[su + ii] * s_D[dk + ii * d3];
                s_tmp[e] = acc;
            }
        }
        __syncthreads();

        // wait for this edge's weights (each thread waits individually)
        mbar_wait((i & 1) ? mbar1 : mbar0, (i >> 1) & 1);

        const float4* w4 = (const float4*)(smem + ((i & 1) ? SM_BUF1 : SM_BUF0));

        // ---- phase 4 ----
        float4 aA = make_float4(0.f,0.f,0.f,0.f);
        {
            float tv;
            float4 w;
            w = w4[rA * 16 + cA];            tv = s_tmp[rA];
            aA.x += w.x*tv; aA.y += w.y*tv; aA.z += w.z*tv; aA.w += w.w*tv;
            w = w4[(rA + 16) * 16 + cA];     tv = s_tmp[rA + 16];
            aA.x += w.x*tv; aA.y += w.y*tv; aA.z += w.z*tv; aA.w += w.w*tv;
            w = w4[(rA + 32) * 16 + cA];     tv = s_tmp[rA + 32];
            aA.x += w.x*tv; aA.y += w.y*tv; aA.z += w.z*tv; aA.w += w.w*tv;
            w = w4[(rA + 48) * 16 + cA];     tv = s_tmp[rA + 48];
            aA.x += w.x*tv; aA.y += w.y*tv; aA.z += w.z*tv; aA.w += w.w*tv;
            w = w4[2048 + rA * 16 + cA];     tv = s_tmp[672 + rA];
            aA.x += w.x*tv; aA.y += w.y*tv; aA.z += w.z*tv; aA.w += w.w*tv;
            w = w4[2048 + (rA + 16) * 16 + cA]; tv = s_tmp[672 + rA + 16];
            aA.x += w.x*tv; aA.y += w.y*tv; aA.z += w.z*tv; aA.w += w.w*tv;
            w = w4[3136 + rA * 16 + cA];     tv = s_tmp[1088 + rA];
            aA.x += w.x*tv; aA.y += w.y*tv; aA.z += w.z*tv; aA.w += w.w*tv;
        }

        float4 b0 = make_float4(0.f,0.f,0.f,0.f);
        float4 b1 = make_float4(0.f,0.f,0.f,0.f);
        float4 b2 = make_float4(0.f,0.f,0.f,0.f);
        {
            float4 w; const float* tp;
            w = w4[1024 + rB * 8 + cB];        tp = s_tmp + 64 + rB * 3;
            b0.x+=w.x*tp[0]; b0.y+=w.y*tp[0]; b0.z+=w.z*tp[0]; b0.w+=w.w*tp[0];
            b1.x+=w.x*tp[1]; b1.y+=w.y*tp[1]; b1.z+=w.z*tp[1]; b1.w+=w.w*tp[1];
            b2.x+=w.x*tp[2]; b2.y+=w.y*tp[2]; b2.z+=w.z*tp[2]; b2.w+=w.w*tp[2];
            w = w4[1024 + (rB + 32) * 8 + cB]; tp = s_tmp + 64 + (rB + 32) * 3;
            b0.x+=w.x*tp[0]; b0.y+=w.y*tp[0]; b0.z+=w.z*tp[0]; b0.w+=w.w*tp[0];
            b1.x+=w.x*tp[1]; b1.y+=w.y*tp[1]; b1.z+=w.z*tp[1]; b1.w+=w.w*tp[1];
            b2.x+=w.x*tp[2]; b2.y+=w.y*tp[2]; b2.z+=w.z*tp[2]; b2.w+=w.w*tp[2];
            w = w4[1792 + rB * 8 + cB];        tp = s_tmp + 576 + rB * 3;
            b0.x+=w.x*tp[0]; b0.y+=w.y*tp[0]; b0.z+=w.z*tp[0]; b0.w+=w.w*tp[0];
            b1.x+=w.x*tp[1]; b1.y+=w.y*tp[1]; b1.z+=w.z*tp[1]; b1.w+=w.w*tp[1];
            b2.x+=w.x*tp[2]; b2.y+=w.y*tp[2]; b2.z+=w.z*tp[2]; b2.w+=w.w*tp[2];
            w = w4[2688 + rB * 8 + cB];        tp = s_tmp + 864 + rB * 3;
            b0.x+=w.x*tp[0]; b0.y+=w.y*tp[0]; b0.z+=w.z*tp[0]; b0.w+=w.w*tp[0];
            b1.x+=w.x*tp[1]; b1.y+=w.y*tp[1]; b1.z+=w.z*tp[1]; b1.w+=w.w*tp[1];
            b2.x+=w.x*tp[2]; b2.y+=w.y*tp[2]; b2.z+=w.z*tp[2]; b2.w+=w.w*tp[2];
            if (rB < 16) {
                w = w4[3008 + rB * 8 + cB];    tp = s_tmp + 1040 + rB * 3;
                b0.x+=w.x*tp[0]; b0.y+=w.y*tp[0]; b0.z+=w.z*tp[0]; b0.w+=w.w*tp[0];
                b1.x+=w.x*tp[1]; b1.y+=w.y*tp[1]; b1.z+=w.z*tp[1]; b1.w+=w.w*tp[1];
                b2.x+=w.x*tp[2]; b2.y+=w.y*tp[2]; b2.z+=w.z*tp[2]; b2.w+=w.w*tp[2];
            }
        }

        float4 c0 = make_float4(0.f,0.f,0.f,0.f);
        float4 c1 = make_float4(0.f,0.f,0.f,0.f);
        float4 c2 = make_float4(0.f,0.f,0.f,0.f);
        float4 c3 = make_float4(0.f,0.f,0.f,0.f);
        float4 c4 = make_float4(0.f,0.f,0.f,0.f);
        {
            float4 w = w4[1536 + rC * 4 + cC];
            const float* tp = s_tmp + 256 + rC * 5;
            float t0=tp[0], t1=tp[1], t2=tp[2], t3=tp[3], t4=tp[4];
            c0.x+=w.x*t0; c0.y+=w.y*t0; c0.z+=w.z*t0; c0.w+=w.w*t0;
            c1.x+=w.x*t1; c1.y+=w.y*t1; c1.z+=w.z*t1; c1.w+=w.w*t1;
            c2.x+=w.x*t2; c2.y+=w.y*t2; c2.z+=w.z*t2; c2.w+=w.w*t2;
            c3.x+=w.x*t3; c3.y+=w.y*t3; c3.z+=w.z*t3; c3.w+=w.w*t3;
            c4.x+=w.x*t4; c4.y+=w.y*t4; c4.z+=w.z*t4; c4.w+=w.w*t4;
            w = w4[wbaseC + uC * 4 + cC];
            tp = s_tmp + tbaseC + uC * 5;
            t0=tp[0]; t1=tp[1]; t2=tp[2]; t3=tp[3]; t4=tp[4];
            c0.x+=w.x*t0; c0.y+=w.y*t0; c0.z+=w.z*t0; c0.w+=w.w*t0;
            c1.x+=w.x*t1; c1.y+=w.y*t1; c1.z+=w.z*t1; c1.w+=w.w*t1;
            c2.x+=w.x*t2; c2.y+=w.y*t2; c2.z+=w.z*t2; c2.w+=w.w*t2;
            c3.x+=w.x*t3; c3.y+=w.y*t3; c3.z+=w.z*t3; c3.w+=w.w*t3;
            c4.x+=w.x*t4; c4.y+=w.y*t4; c4.z+=w.z*t4; c4.w+=w.w*t4;
        }

        // store all partials to disjoint scratch, single barrier
        ((float4*)s_red)[t] = aA;                                  // [0,1024) floats
        { float4* rb = (float4*)(s_red + 1024) + t * 3; rb[0]=b0; rb[1]=b1; rb[2]=b2; }  // [1024,4096)
        { float4* rc = (float4*)(s_red + 4096) + t * 5; rc[0]=c0; rc[1]=c1; rc[2]=c2; rc[3]=c3; rc[4]=c4; } // [4096,9216)
        __syncthreads();

        // stream next-next edge into the buffer we just finished reading
        int z2 = z + 2 * stride;
        if (t == 0 && z2 < n_edges)
            tma_issue(sbase + ((i & 1) ? SM_BUF1 : SM_BUF0),
                      W + (size_t)z2 * 13824, (i & 1) ? mbar1 : mbar0);

        // reductions: threads 0-63 -> region A, 64-159 -> B, 160-239 -> C
        float* outrow = O + (size_t)z * 240;
        if (t < 64) {
            float s0=0.f,s1=0.f,s2=0.f,s3=0.f;
            #pragma unroll
            for (int r = 0; r < 16; r += 4) {
                s0 += s_red[(r    ) * 64 + t];
                s1 += s_red[(r + 1) * 64 + t];
                s2 += s_red[(r + 2) * 64 + t];
                s3 += s_red[(r + 3) * 64 + t];
            }
            outrow[t] = PW0 * ((s0 + s1) + (s2 + s3));
        } else if (t < 160) {
            int tt = t - 64;
            int w3 = tt / 3, k = tt - w3 * 3;
            int c = w3 >> 2, comp = w3 & 3;
            const float* rb = s_red + 1024;
            float s0=0.f,s1=0.f,s2=0.f,s3=0.f;
            #pragma unroll
            for (int r = 0; r < 32; r += 4) {
                s0 += rb[(((r    ) * 8 + c) * 3 + k) * 4 + comp];
                s1 += rb[(((r + 1) * 8 + c) * 3 + k) * 4 + comp];
                s2 += rb[(((r + 2) * 8 + c) * 3 + k) * 4 + comp];
                s3 += rb[(((r + 3) * 8 + c) * 3 + k) * 4 + comp];
            }
            outrow[64 + w3 * 3 + k] = PW1 * ((s0 + s1) + (s2 + s3));
        } else if (t < 240) {
            int tt = t - 160;
            int w3 = tt / 5, k = tt - w3 * 5;
            int c = w3 >> 2, comp = w3 & 3;
            const float* rc = s_red + 4096;
            float s0=0.f,s1=0.f,s2=0.f,s3=0.f;
            #pragma unroll
            for (int r = 0; r < 64; r += 4) {
                s0 += rc[(((r    ) * 4 + c) * 5 + k) * 4 + comp];
                s1 += rc[(((r + 1) * 4 + c) * 5 + k) * 4 + comp];
                s2 += rc[(((r + 2) * 4 + c) * 5 + k) * 4 + comp];
                s3 += rc[(((r + 3) * 4 + c) * 5 + k) * 4 + comp];
            }
            outrow[160 + w3 * 5 + k] = PW2 * ((s0 + s1) + (s2 + s3));
        }
        __syncthreads();
    }
}

// ---------------------------------------------------------------------------

extern "C" void kernel_launch(void* const* d_in, const int* in_sizes, int n_in,
                              void* d_out, int out_size) {
    const float* u = (const float*)d_in[0];
    const float* v = (const float*)d_in[1];
    const float* w = (const float*)d_in[2];
    float* out = (float*)d_out;

    const int n_edges = in_sizes[0] / 240;

    cudaFuncSetAttribute(tp_main_kernel,
                         cudaFuncAttributeMaxDynamicSharedMemorySize, SM_TOTAL);

    w3j_setup_kernel<<<1, 384>>>();
    tp_main_kernel<<<1024, 256, SM_TOTAL>>>(u, v, w, out, n_edges);
    (void)n_in; (void)out_size;
}

// round 13
// speedup vs baseline: 1.1224x; 1.1224x over previous
#include <cuda_runtime.h>
#include <cuda_bf16.h>
#include <math.h>
#include <stdint.h>

// ---------------------------------------------------------------------------
// FullyConnectedTP (e3nn): IN 64x0e+32x1o+16x2e (240), SH 9, OUT 240,
// per-edge weights 13824 fp32, N_EDGES 16384.
//
// R11: warp-per-edge, ZERO block-wide barriers in the hot path. Warps drift
// freely -> continuous DRAM demand (fixes the 50-60% DRAM phase-lock seen in
// every block-barrier design R2/R3/R5/R10). Weights read once, coalesced
// LDG.128, directly from global; cross-lane reductions via shfl_xor.
// ---------------------------------------------------------------------------

#define NPATH 11

__constant__ int C_L1[NPATH]    = {0,0,0,1,1,1,1,2,2,2,2};
__constant__ int C_L2[NPATH]    = {0,1,2,0,1,1,2,0,1,2,2};
__constant__ int C_L3[NPATH]    = {0,1,2,1,0,2,1,2,1,0,2};
__constant__ int C_COFF[NPATH]  = {0,1,10,35,44,53,98,143,168,213,238};
__constant__ int C_CSZ[NPATH]   = {1,9,25,9,9,45,45,25,45,25,125};
__constant__ int C_DOFF[NPATH]  = {0,1,4,9,18,21,36,45,70,85,90};
__constant__ int C_TOFF[NPATH]  = {0,64,256,576,672,704,864,960,1040,1088,1104};
__constant__ int C_INOFF[NPATH] = {0,0,0,64,64,64,64,160,160,160,160};
__constant__ int C_SHOFF[NPATH] = {0,1,4,0,1,1,4,0,1,4,4};

__device__ float    g_w3j[363];
__device__ unsigned g_desc2[115];
__device__ unsigned g_desc3[1184];

// ---------------------------------------------------------------------------
// Setup kernel (FP32): wigner 3j + descriptor tables (same math as reference)
// ---------------------------------------------------------------------------

__device__ __forceinline__ float d_fact(int n) {
    const float F[9] = {1.f, 1.f, 2.f, 6.f, 24.f, 120.f, 720.f, 5040.f, 40320.f};
    return F[n];
}

__device__ float su2_cg_coeff(int j1, int m1, int j2, int m2, int j3, int m3) {
    if (m3 != m1 + m2) return 0.0f;
    int vmin = -j1 + j2 + m3;
    if (-j1 + m1 > vmin) vmin = -j1 + m1;
    if (0 > vmin) vmin = 0;
    int vmax = j2 + j3 + m1;
    if (j3 - j1 + j2 < vmax) vmax = j3 - j1 + j2;
    if (j3 + m3 < vmax) vmax = j3 + m3;
    float C = sqrtf((float)(2 * j3 + 1)
                    * d_fact(j3 + j1 - j2) * d_fact(j3 - j1 + j2) * d_fact(j1 + j2 - j3)
                    * d_fact(j3 + m3) * d_fact(j3 - m3)
                    / (d_fact(j1 + j2 + j3 + 1) * d_fact(j1 - m1) * d_fact(j1 + m1)
                       * d_fact(j2 - m2) * d_fact(j2 + m2)));
    float S = 0.0f;
    for (int v = vmin; v <= vmax; ++v) {
        float sgn = ((v + j2 + m2) & 1) ? -1.0f : 1.0f;
        S += sgn * d_fact(j2 + j3 + m1 - v) * d_fact(j1 - m1 + v)
             / (d_fact(v) * d_fact(j3 - j1 + j2 - v) * d_fact(j3 + m3 - v)
                * d_fact(v + j1 - j2 - m3));
    }
    return C * S;
}

__device__ void q_entry(int l, int r, int c, float& qre, float& qim) {
    const float s = 0.70710678118654752440f;
    float re = 0.0f, im = 0.0f;
    int m = r - l;
    if (m < 0) {
        if (c == l - m)      re = s;
        else if (c == l + m) im = -s;
    } else if (m == 0) {
        if (c == l) re = 1.0f;
    } else {
        float sg = (m & 1) ? -1.0f : 1.0f;
        if (c == l + m)      re = sg * s;
        else if (c == l - m) im = sg * s;
    }
    float ore, oim;
    switch (l & 3) {
        case 0: ore =  re; oim =  im; break;
        case 1: ore =  im; oim = -re; break;
        case 2: ore = -re; oim = -im; break;
        default: ore = -im; oim =  re; break;
    }
    qre = ore; qim = oim;
}

__global__ void w3j_setup_kernel() {
    __shared__ float sC[363];
    __shared__ float sInv[NPATH];
    int e = threadIdx.x;

    if (e < 363) {
        int p = 0;
        while (p < NPATH - 1 && e >= C_COFF[p + 1]) ++p;
        int local = e - C_COFF[p];
        int l1 = C_L1[p], l2 = C_L2[p], l3 = C_L3[p];
        int d2 = 2 * l2 + 1, d3 = 2 * l3 + 1;
        int a = local / (d2 * d3);
        int rem = local - a * (d2 * d3);
        int b = rem / d3;
        int c = rem - b * d3;
        float acc = 0.0f;
        for (int i = 0; i <= 2 * l1; ++i) {
            for (int k = 0; k <= 2 * l2; ++k) {
                int m1 = i - l1, m2 = k - l2, m3 = m1 + m2;
                if (m3 < -l3 || m3 > l3) continue;
                int n = l3 + m3;
                float cg = su2_cg_coeff(l1, m1, l2, m2, l3, m3);
                if (cg == 0.0f) continue;
                float q1r, q1i, q2r, q2i, q3r, q3i;
                q_entry(l1, i, a, q1r, q1i);
                q_entry(l2, k, b, q2r, q2i);
                q_entry(l3, c, n, q3r, q3i);
                q3i = -q3i;
                float tr = q1r * q2r - q1i * q2i;
                float ti = q1r * q2i + q1i * q2r;
                float ur = tr * q3r - ti * q3i;
                acc += ur * cg;
            }
        }
        sC[e] = acc;
    }
    __syncthreads();
    if (e < NPATH) {
        float ss = 0.f;
        int base = C_COFF[e], sz = C_CSZ[e];
        for (int q = 0; q < sz; ++q) ss += sC[base + q] * sC[base + q];
        sInv[e] = rsqrtf(ss);
    }
    __syncthreads();
    if (e < 363) {
        int p = 0;
        while (p < NPATH - 1 && e >= C_COFF[p + 1]) ++p;
        g_w3j[e] = sC[e] * sInv[p];
    }

    if (e < 115) {
        int p = 0;
        while (p < NPATH - 1 && e >= C_DOFF[p + 1]) ++p;
        int local = e - C_DOFF[p];
        int d2 = 2 * C_L2[p] + 1, d3 = 2 * C_L3[p] + 1;
        int i = local / d3;
        int k = local - i * d3;
        unsigned base = C_COFF[p] + (i * d2) * d3 + k;
        g_desc2[e] = base | ((unsigned)d3 << 10) | ((unsigned)d2 << 13)
                   | ((unsigned)C_SHOFF[p] << 16);
    }
    for (int e3 = e; e3 < 1184; e3 += blockDim.x) {
        int p = 0;
        while (p < NPATH - 1 && e3 >= C_TOFF[p + 1]) ++p;
        int local = e3 - C_TOFF[p];
        int d1 = 2 * C_L1[p] + 1, d3 = 2 * C_L3[p] + 1;
        int u = local / d3;
        int k = local - u * d3;
        unsigned su = C_INOFF[p] + u * d1;
        unsigned dk = C_DOFF[p] + k;
        g_desc3[e3] = su | (dk << 8) | ((unsigned)d3 << 15) | ((unsigned)d1 << 18);
    }
}

// ---------------------------------------------------------------------------
// Main kernel: one warp per edge.
// ---------------------------------------------------------------------------

#define PW0 0.09449111825230679f
#define PW1 0.14433756729740643f
#define PW2 0.19764235376052372f

#define WARPS_PB 8
// shared layout (bytes): tables then per-warp slabs
#define SM_W3J    0                 /* 363 floats -> 1452, pad 1456 */
#define SM_DESC2  1456              /* 115 u32 -> 460, pad 464 */
#define SM_DESC3  1920              /* 1184 u32 -> 4736 */
#define SM_SLABS  6656
// per-warp slab (floats): u[0,240) D[240,360) tmp[360,1544) v[1544,1556) pad->1560
#define SLAB_F    1560
#define SM_TOTAL  (SM_SLABS + WARPS_PB * SLAB_F * 4)   /* 6656+49920 = 56576 */

#define FMA4(acc, wv, s) \
    { acc.x += wv.x*(s); acc.y += wv.y*(s); acc.z += wv.z*(s); acc.w += wv.w*(s); }

__device__ __forceinline__ void shfl_red4(float4& a, int m) {
    a.x += __shfl_xor_sync(0xffffffffu, a.x, m);
    a.y += __shfl_xor_sync(0xffffffffu, a.y, m);
    a.z += __shfl_xor_sync(0xffffffffu, a.z, m);
    a.w += __shfl_xor_sync(0xffffffffu, a.w, m);
}

__global__ __launch_bounds__(32 * WARPS_PB) void tp_main_kernel(
    const float* __restrict__ U, const float* __restrict__ V,
    const float* __restrict__ W, float* __restrict__ O, int n_edges)
{
    extern __shared__ char smem[];
    float*    t_w3j   = (float*)(smem + SM_W3J);
    unsigned* t_desc2 = (unsigned*)(smem + SM_DESC2);
    unsigned* t_desc3 = (unsigned*)(smem + SM_DESC3);

    const int t    = threadIdx.x;
    const int lane = t & 31;
    const int wid  = t >> 5;

    // stage tables once per block (only block-wide barrier in the kernel)
    for (int e = t; e < 363;  e += 32 * WARPS_PB) t_w3j[e]   = g_w3j[e];
    for (int e = t; e < 115;  e += 32 * WARPS_PB) t_desc2[e] = g_desc2[e];
    for (int e = t; e < 1184; e += 32 * WARPS_PB) t_desc3[e] = g_desc3[e];
    __syncthreads();

    const int z = blockIdx.x * WARPS_PB + wid;
    if (z >= n_edges) return;

    float* slab  = (float*)(smem + SM_SLABS) + wid * SLAB_F;
    float* s_u   = slab;
    float* s_D   = slab + 240;
    float* s_tmp = slab + 360;
    float* s_v   = slab + 1544;

    // ---- stage u, v (warp-local) ----------------------------------------
    {
        const float* urow = U + (size_t)z * 240;
        for (int j = lane; j < 240; j += 32) s_u[j] = urow[j];
        if (lane < 9) s_v[lane] = V[(size_t)z * 9 + lane];
    }
    __syncwarp();

    // ---- phase 2: D[115] -------------------------------------------------
    for (int e = lane; e < 115; e += 32) {
        unsigned d = t_desc2[e];
        int base = d & 1023;
        int d3   = (d >> 10) & 7;
        int d2   = (d >> 13) & 7;
        int sh   = (d >> 16) & 15;
        float acc = 0.f;
        for (int j = 0; j < d2; ++j)
            acc += t_w3j[base + j * d3] * s_v[sh + j];
        s_D[e] = acc;
    }
    __syncwarp();

    // ---- phase 3: tmp[1184] ---------------------------------------------
    for (int e = lane; e < 1184; e += 32) {
        unsigned d = t_desc3[e];
        int su = d & 255;
        int dk = (d >> 8) & 127;
        int d3 = (d >> 15) & 7;
        int d1 = (d >> 18) & 7;
        float acc = 0.f;
        for (int i = 0; i < d1; ++i)
            acc += s_u[su + i] * s_D[dk + i * d3];
        s_tmp[e] = acc;
    }
    __syncwarp();

    // ---- phase 4: weight contraction (coalesced LDG.128, warp-local) ----
    const float4* __restrict__ w4 = (const float4*)(W + (size_t)z * 13824);
    float* outrow = O + (size_t)z * 240;

    // region A: out l3=0 (64 outputs). rows of 16 float4; 2 rows per iter.
    {
        const int c = lane & 15, h = lane >> 4;
        float4 a = make_float4(0.f, 0.f, 0.f, 0.f);
        #pragma unroll 4
        for (int it = 0; it < 32; ++it) {          // p0: 64 rows
            int u = 2 * it + h;
            float4 wv = w4[u * 16 + c];
            FMA4(a, wv, s_tmp[u]);
        }
        #pragma unroll 4
        for (int it = 0; it < 16; ++it) {          // p4: 32 rows
            int u = 2 * it + h;
            float4 wv = w4[2048 + u * 16 + c];
            FMA4(a, wv, s_tmp[672 + u]);
        }
        #pragma unroll 4
        for (int it = 0; it < 8; ++it) {           // p9: 16 rows
            int u = 2 * it + h;
            float4 wv = w4[3136 + u * 16 + c];
            FMA4(a, wv, s_tmp[1088 + u]);
        }
        shfl_red4(a, 16);
        if (h == 0) {
            float4 o = make_float4(PW0 * a.x, PW0 * a.y, PW0 * a.z, PW0 * a.w);
            ((float4*)outrow)[c] = o;
        }
    }

    // region B: out l3=1 (32 w3 x 3 k). rows of 8 float4; 4 rows per iter.
    {
        const int c = lane & 7, g = lane >> 3;
        float4 b0 = make_float4(0.f,0.f,0.f,0.f);
        float4 b1 = make_float4(0.f,0.f,0.f,0.f);
        float4 b2 = make_float4(0.f,0.f,0.f,0.f);
        #pragma unroll 4
        for (int it = 0; it < 16; ++it) {          // p1: 64 rows
            int u = 4 * it + g;
            float4 wv = w4[1024 + u * 8 + c];
            const float* tp = s_tmp + 64 + u * 3;
            FMA4(b0, wv, tp[0]); FMA4(b1, wv, tp[1]); FMA4(b2, wv, tp[2]);
        }
        #pragma unroll 4
        for (int it = 0; it < 8; ++it) {           // p3: 32 rows
            int u = 4 * it + g;
            float4 wv = w4[1792 + u * 8 + c];
            const float* tp = s_tmp + 576 + u * 3;
            FMA4(b0, wv, tp[0]); FMA4(b1, wv, tp[1]); FMA4(b2, wv, tp[2]);
        }
        #pragma unroll 4
        for (int it = 0; it < 8; ++it) {           // p6: 32 rows
            int u = 4 * it + g;
            float4 wv = w4[2688 + u * 8 + c];
            const float* tp = s_tmp + 864 + u * 3;
            FMA4(b0, wv, tp[0]); FMA4(b1, wv, tp[1]); FMA4(b2, wv, tp[2]);
        }
        #pragma unroll 4
        for (int it = 0; it < 4; ++it) {           // p8: 16 rows
            int u = 4 * it + g;
            float4 wv = w4[3008 + u * 8 + c];
            const float* tp = s_tmp + 1040 + u * 3;
            FMA4(b0, wv, tp[0]); FMA4(b1, wv, tp[1]); FMA4(b2, wv, tp[2]);
        }
        shfl_red4(b0, 8);  shfl_red4(b0, 16);
        shfl_red4(b1, 8);  shfl_red4(b1, 16);
        shfl_red4(b2, 8);  shfl_red4(b2, 16);
        if (g == 0) {
            float* ob = outrow + 64 + 12 * c;      // w3 = 4c..4c+3
            ob[0]  = PW1 * b0.x; ob[1]  = PW1 * b1.x; ob[2]  = PW1 * b2.x;
            ob[3]  = PW1 * b0.y; ob[4]  = PW1 * b1.y; ob[5]  = PW1 * b2.y;
            ob[6]  = PW1 * b0.z; ob[7]  = PW1 * b1.z; ob[8]  = PW1 * b2.z;
            ob[9]  = PW1 * b0.w; ob[10] = PW1 * b1.w; ob[11] = PW1 * b2.w;
        }
    }

    // region C: out l3=2 (16 w3 x 5 k). rows of 4 float4; 8 rows per iter.
    {
        const int c = lane & 3, g = lane >> 2;
        float4 c0 = make_float4(0.f,0.f,0.f,0.f);
        float4 c1 = make_float4(0.f,0.f,0.f,0.f);
        float4 c2 = make_float4(0.f,0.f,0.f,0.f);
        float4 c3 = make_float4(0.f,0.f,0.f,0.f);
        float4 c4 = make_float4(0.f,0.f,0.f,0.f);
        #pragma unroll 4
        for (int it = 0; it < 8; ++it) {           // p2: 64 rows
            int u = 8 * it + g;
            float4 wv = w4[1536 + u * 4 + c];
            const float* tp = s_tmp + 256 + u * 5;
            FMA4(c0, wv, tp[0]); FMA4(c1, wv, tp[1]); FMA4(c2, wv, tp[2]);
            FMA4(c3, wv, tp[3]); FMA4(c4, wv, tp[4]);
        }
        #pragma unroll 4
        for (int it = 0; it < 4; ++it) {           // p5: 32 rows
            int u = 8 * it + g;
            float4 wv = w4[2560 + u * 4 + c];
            const float* tp = s_tmp + 704 + u * 5;
            FMA4(c0, wv, tp[0]); FMA4(c1, wv, tp[1]); FMA4(c2, wv, tp[2]);
            FMA4(c3, wv, tp[3]); FMA4(c4, wv, tp[4]);
        }
        #pragma unroll
        for (int it = 0; it < 2; ++it) {           // p7: 16 rows
            int u = 8 * it + g;
            float4 wv = w4[2944 + u * 4 + c];
            const float* tp = s_tmp + 960 + u * 5;
            FMA4(c0, wv, tp[0]); FMA4(c1, wv, tp[1]); FMA4(c2, wv, tp[2]);
            FMA4(c3, wv, tp[3]); FMA4(c4, wv, tp[4]);
        }
        #pragma unroll
        for (int it = 0; it < 2; ++it) {           // p10: 16 rows
            int u = 8 * it + g;
            float4 wv = w4[3392 + u * 4 + c];
            const float* tp = s_tmp + 1104 + u * 5;
            FMA4(c0, wv, tp[0]); FMA4(c1, wv, tp[1]); FMA4(c2, wv, tp[2]);
            FMA4(c3, wv, tp[3]); FMA4(c4, wv, tp[4]);
        }
        shfl_red4(c0, 4); shfl_red4(c0, 8); shfl_red4(c0, 16);
        shfl_red4(c1, 4); shfl_red4(c1, 8); shfl_red4(c1, 16);
        shfl_red4(c2, 4); shfl_red4(c2, 8); shfl_red4(c2, 16);
        shfl_red4(c3, 4); shfl_red4(c3, 8); shfl_red4(c3, 16);
        shfl_red4(c4, 4); shfl_red4(c4, 8); shfl_red4(c4, 16);
        if (g == 0) {
            float* oc = outrow + 160 + 20 * c;     // w3 = 4c..4c+3
            oc[0]  = PW2 * c0.x; oc[1]  = PW2 * c1.x; oc[2]  = PW2 * c2.x;
            oc[3]  = PW2 * c3.x; oc[4]  = PW2 * c4.x;
            oc[5]  = PW2 * c0.y; oc[6]  = PW2 * c1.y; oc[7]  = PW2 * c2.y;
            oc[8]  = PW2 * c3.y; oc[9]  = PW2 * c4.y;
            oc[10] = PW2 * c0.z; oc[11] = PW2 * c1.z; oc[12] = PW2 * c2.z;
            oc[13] = PW2 * c3.z; oc[14] = PW2 * c4.z;
            oc[15] = PW2 * c0.w; oc[16] = PW2 * c1.w; oc[17] = PW2 * c2.w;
            oc[18] = PW2 * c3.w; oc[19] = PW2 * c4.w;
        }
    }
}

// ---------------------------------------------------------------------------

extern "C" void kernel_launch(void* const* d_in, const int* in_sizes, int n_in,
                              void* d_out, int out_size) {
    const float* u = (const float*)d_in[0];
    const float* v = (const float*)d_in[1];
    const float* w = (const float*)d_in[2];
    float* out = (float*)d_out;

    const int n_edges = in_sizes[0] / 240;
    const int blocks = (n_edges + WARPS_PB - 1) / WARPS_PB;

    cudaFuncSetAttribute(tp_main_kernel,
                         cudaFuncAttributeMaxDynamicSharedMemorySize, SM_TOTAL);

    w3j_setup_kernel<<<1, 384>>>();
    tp_main_kernel<<<blocks, 32 * WARPS_PB, SM_TOTAL>>>(u, v, w, out, n_edges);
    (void)n_in; (void)out_size;
}